// round 14
// baseline (speedup 1.0000x reference)
#include <cuda_runtime.h>
#include <cstdint>

#define B_    8
#define CI_   512
#define CO_   256
#define HW_   64
#define YP_   136
#define YPP   (YP_ * YP_)
#define ZS_   128
#define NQUAD 65
#define NQ2   (NQUAD * NQUAD)                 // 4225
#define NTOT  (B_ * NQ2)                      // 33800 quads
#define MT_   128                             // M per CTA
#define NTILES ((NTOT + MT_ - 1) / MT_)       // 265
#define NCH   16
#define CONV_SMEM (2 * (16384 + 16384))       // 64 KB: double-buffered A(16K) + B(16K)

// B frag layout: [half][tap][ch] blocks of 4096 floats: [kt][wn][p][lane][c]
__device__ float g_wf[2 * 9 * 16 * 4096];
__device__ float g_xr[B_ * CI_ * HW_ * HW_];       // tf32-rounded x copy
__device__ float g_y[B_ * CO_ * YPP];              // padded intermediate (pad stays 0)

__device__ __forceinline__ uint32_t f2tf32(float f) {   // RN-to-even tf32 bits
    uint32_t u = __float_as_uint(f);
    u = u + 0xFFFu + ((u >> 13) & 1u);
    return u & 0xFFFFE000u;
}
__device__ __forceinline__ uint32_t sm_u32(const void* p) {
    uint32_t a;
    asm("{ .reg .u64 t; cvta.to.shared.u64 t, %1; cvt.u32.u64 %0, t; }" : "=r"(a) : "l"(p));
    return a;
}

// D(16x8) += A(16x8) * B(8x8), tf32. a packed as (v0,v1,v2,v3)=((m,k),(m,k+4),(m+8,k),(m+8,k+4))
__device__ __forceinline__ void mma8(float* c, float4 a, float b0, float b1) {
    asm volatile(
        "mma.sync.aligned.m16n8k8.row.col.f32.tf32.tf32.f32 "
        "{%0,%1,%2,%3}, {%4,%5,%6,%7}, {%8,%9}, {%0,%1,%2,%3};"
        : "+f"(c[0]), "+f"(c[1]), "+f"(c[2]), "+f"(c[3])
        : "r"(__float_as_uint(a.x)), "r"(__float_as_uint(a.z)),
          "r"(__float_as_uint(a.y)), "r"(__float_as_uint(a.w)),
          "r"(__float_as_uint(b0)), "r"(__float_as_uint(b1)));
}

// ---------------- parity tables as constexpr functions ----------------
__host__ __device__ constexpr int pc_nt(int P) { return P == 0 ? 4 : (P == 3 ? 1 : 2); }
__host__ __device__ constexpr int pc_sh(int P, int j) {
    return P == 0 ? j
         : P == 1 ? (j == 0 ? 1 : 3)
         : P == 2 ? (j == 0 ? 2 : 3)
         : 3;
}
__host__ __device__ constexpr int pc_tp(int P, int j) {
    return P == 0 ? (j == 0 ? 0 : j == 1 ? 2 : j == 2 ? 6 : 8)
         : P == 1 ? (j == 0 ? 1 : 7)
         : P == 2 ? (j == 0 ? 3 : 5)
         : 4;
}

// ---------------- x -> tf32-rounded copy ----------------
__global__ void roundx_kernel(const float* __restrict__ x) {
    int i = blockIdx.x * 256 + threadIdx.x;
    float4 v = ((const float4*)x)[i];
    uint4 u;
    u.x = f2tf32(v.x); u.y = f2tf32(v.y); u.z = f2tf32(v.z); u.w = f2tf32(v.w);
    ((uint4*)g_xr)[i] = u;
}

// ---------------- prep: demodulate + flip + tf32-round, B fragment layout ----------------
__global__ void prep_kernel(const float* __restrict__ w) {
    __shared__ float red[256];
    const int o = blockIdx.x, tid = threadIdx.x;
    const float wsc = 1.0f / sqrtf((float)(CI_ * 9));
    const float* wo = w + o * (CI_ * 9);
    float s = 0.f;
    for (int idx = tid; idx < CI_ * 9; idx += 256) {
        float v = wo[idx] * wsc;
        s += v * v;
    }
    red[tid] = s;
    __syncthreads();
    for (int st = 128; st > 0; st >>= 1) {
        if (tid < st) red[tid] += red[tid + st];
        __syncthreads();
    }
    const float scale = wsc * rsqrtf(red[0] + 1e-6f);
    const int half = o >> 7, o7 = o & 127;
    const int wn = o7 >> 5, c5 = o7 & 31, nt = c5 >> 3, cn = c5 & 7;
    const int p = nt >> 1;
    for (int idx = tid; idx < CI_ * 9; idx += 256) {
        int i = idx / 9, t = idx % 9, kh = t / 3, kw = t % 3;
        float v = wo[i * 9 + (2 - kh) * 3 + (2 - kw)] * scale;       // spatial flip
        int ch = i >> 5, k5 = i & 31, kt = k5 >> 3, ck = k5 & 7;
        int lane = cn * 4 + (ck & 3), reg = ck >> 2;
        int c = (nt & 1) * 2 + reg;
        g_wf[(size_t)((half * 9 + t) * 16 + ch) * 4096
             + (size_t)(((kt * 4 + wn) * 2 + p) * 32 + lane) * 4 + c]
            = __uint_as_float(f2tf32(v));
    }
}

// ---------------- transposed conv, one parity, TF32 mma.sync, 2 CTA/SM ----------------
template <int P>
__global__ void __launch_bounds__(256, 2) conv_mma() {
    constexpr int NT = pc_nt(P);
    constexpr int S  = NCH * NT;               // steps: (ch, tap) pairs
    extern __shared__ float4 smem4[];
    float4* smA = smem4;                       // 2 bufs x 1024 float4 (A frag tile)
    float4* smB = smem4 + 2048;                // 2 bufs x 1024 float4 (B tap slice, N=128)
    const uint32_t smA_u = sm_u32(smA);
    const uint32_t smB_u = sm_u32(smB);

    const int tid = threadIdx.x, lane = tid & 31, warp = tid >> 5;
    const int wm = warp >> 2, wn = warp & 3;
    const int nt0 = blockIdx.x * MT_;
    const int half = blockIdx.y;

    // ---- staging precompute: per (i,row) SIGNED src base (halo -1,-1 folded) + shift validity ----
    int32_t srcb[4][2];                        // signed! (edge quads go slightly negative)
    uint32_t vmask = 0;                        // bit ((i*2+row)*4 + sh)
    int kOff0[4];
#pragma unroll
    for (int i = 0; i < 4; i++) {
        const int e = tid + i * 256;
        const int mtkt = e >> 5, sl = e & 31;
        kOff0[i] = ((mtkt & 3) * 8 + (sl & 3)) << 12;          // kl * 4096
        const int m0 = (mtkt >> 2) * 16 + (sl >> 2);
#pragma unroll
        for (int row = 0; row < 2; row++) {
            const int gm = nt0 + m0 + row * 8;
            const int b = gm / NQ2, r = gm - b * NQ2;
            const int qa = r / NQUAD, qb = r - qa * NQUAD;
            const bool mok = gm < NTOT;
            srcb[i][row] = mok ? ((b * CI_) << 12) + (qa - 1) * HW_ + (qb - 1) : 0;
#pragma unroll
            for (int sh = 0; sh < 4; sh++) {
                const int iy = qa - 1 + (sh >> 1), ix = qb - 1 + (sh & 1);
                if (mok && (unsigned)iy < HW_ && (unsigned)ix < HW_)
                    vmask |= 1u << ((i * 2 + row) * 4 + sh);
            }
        }
    }

    // stage step st into buffer buf: A (one shift, zfill OOB) + B (one tap slice, coalesced)
    auto stage = [&](int st, int buf) {
        const int ch = st / NT, j = st - ch * NT;
        const int sh = pc_sh(P, j);
        const int sdel = (sh >> 1) * HW_ + (sh & 1);
        const int cco = ch << 17;
#pragma unroll
        for (int i = 0; i < 4; i++) {
            const uint32_t dst0 = smA_u + (uint32_t)((buf * 1024 + tid + i * 256) * 16);
#pragma unroll
            for (int row = 0; row < 2; row++) {
                const uint32_t okn = ((vmask >> ((i * 2 + row) * 4 + sh)) & 1u) << 2;
                const float* src = g_xr + (srcb[i][row] + sdel + cco + kOff0[i]);   // signed sum
                asm volatile("cp.async.ca.shared.global [%0], [%1], 4, %2;"
                             :: "r"(dst0 + row * 8), "l"(src), "r"(okn) : "memory");
                asm volatile("cp.async.ca.shared.global [%0], [%1], 4, %2;"
                             :: "r"(dst0 + row * 8 + 4), "l"(src + (1 << 14)), "r"(okn) : "memory");
            }
        }
        const int tap = pc_tp(P, j);
        const float4* bs = ((const float4*)g_wf) + (size_t)((half * 9 + tap) * 16 + ch) * 1024 + tid;
        const uint32_t bd = smB_u + (uint32_t)((buf * 1024 + tid) * 16);
#pragma unroll
        for (int t = 0; t < 4; t++)
            asm volatile("cp.async.ca.shared.global [%0], [%1], 16;"
                         :: "r"(bd + t * 4096), "l"(bs + t * 256) : "memory");
        asm volatile("cp.async.commit_group;" ::: "memory");
    };

    float acc[4][4][4];                        // [q m-tile][n-tile][frag]
#pragma unroll
    for (int q = 0; q < 4; q++)
#pragma unroll
        for (int n = 0; n < 4; n++)
#pragma unroll
            for (int r = 0; r < 4; r++) acc[q][n][r] = 0.f;

    stage(0, 0);
    asm volatile("cp.async.wait_group 0;" ::: "memory");
    __syncthreads();

    for (int st = 0; st < S; st++) {
        if (st + 1 < S) stage(st + 1, (st + 1) & 1);           // async prefetch
        const int bo = (st & 1);
#pragma unroll
        for (int kt = 0; kt < 4; kt++) {
            float4 af[4], bf[2];
#pragma unroll
            for (int q = 0; q < 4; q++)
                af[q] = smA[bo * 1024 + ((wm * 4 + q) * 4 + kt) * 32 + lane];
#pragma unroll
            for (int p = 0; p < 2; p++)
                bf[p] = smB[bo * 1024 + ((kt * 4 + wn) * 2 + p) * 32 + lane];
#pragma unroll
            for (int q = 0; q < 4; q++) {
                mma8(acc[q][0], af[q], bf[0].x, bf[0].y);
                mma8(acc[q][1], af[q], bf[0].z, bf[0].w);
                mma8(acc[q][2], af[q], bf[1].x, bf[1].y);
                mma8(acc[q][3], af[q], bf[1].z, bf[1].w);
            }
        }
        if (st + 1 < S) {
            asm volatile("cp.async.wait_group 0;" ::: "memory");
            __syncthreads();
        }
    }

    // ---- epilogue: C frag -> g_y (parity pixel per quad) ----
#pragma unroll
    for (int q = 0; q < 4; q++) {
        size_t addr[2]; bool ok[2];
#pragma unroll
        for (int row = 0; row < 2; row++) {
            const int gm = nt0 + wm * 64 + q * 16 + (lane >> 2) + row * 8;
            const int b = gm / NQ2, r = gm - b * NQ2;
            const int qa = r / NQUAD, qb = r - qa * NQUAD;
            const int oy = 2 * qa + (P >> 1), ox = 2 * qb + (P & 1);
            ok[row] = (gm < NTOT) && (oy <= 128) && (ox <= 128);
            addr[row] = (size_t)(b * CO_) * YPP + (size_t)(oy + 1) * YP_ + (ox + 1);
        }
#pragma unroll
        for (int n = 0; n < 4; n++) {
            const int co = half * 128 + wn * 32 + n * 8 + 2 * (lane & 3);
            if (ok[0]) {
                size_t a0 = addr[0] + (size_t)co * YPP;
                g_y[a0] = acc[q][n][0];
                g_y[a0 + YPP] = acc[q][n][1];
            }
            if (ok[1]) {
                size_t a1 = addr[1] + (size_t)co * YPP;
                g_y[a1] = acc[q][n][2];
                g_y[a1 + YPP] = acc[q][n][3];
            }
        }
    }
}

// ---------------- depthwise 4x4 FIR blur, separable row-streaming ----------------
__global__ void blur_kernel(float* __restrict__ z) {
    const int cx = threadIdx.x;
    const int ry = threadIdx.y;
    const int bc = blockIdx.z;
    const int b = bc >> 8;
    const int col = bc & 255;
    const float* yb = g_y + (size_t)(b * CO_ + col) * YPP;
    float* zb = z + (size_t)(b * CO_ + col) * (ZS_ * ZS_);
    const int c0 = cx * 4;
    const int zy0 = ry * 16;

    float4 h0 = {}, h1 = {}, h2 = {};
#pragma unroll
    for (int k = 0; k < 19; k++) {
        const float* row = yb + (size_t)(zy0 + k) * YP_ + c0;
        float4 a = *(const float4*)row;
        float4 e = *(const float4*)(row + 4);
        float4 h;
        h.x = a.x + 3.f * a.y + 3.f * a.z + a.w;
        h.y = a.y + 3.f * a.z + 3.f * a.w + e.x;
        h.z = a.z + 3.f * a.w + 3.f * e.x + e.y;
        h.w = a.w + 3.f * e.x + 3.f * e.y + e.z;
        if (k >= 3) {
            float4 o;
            o.x = (h0.x + 3.f * h1.x + 3.f * h2.x + h.x) * 0.0625f;
            o.y = (h0.y + 3.f * h1.y + 3.f * h2.y + h.y) * 0.0625f;
            o.z = (h0.z + 3.f * h1.z + 3.f * h2.z + h.z) * 0.0625f;
            o.w = (h0.w + 3.f * h1.w + 3.f * h2.w + h.w) * 0.0625f;
            *(float4*)&zb[(size_t)(zy0 + k - 3) * ZS_ + c0] = o;
        }
        h0 = h1; h1 = h2; h2 = h;
    }
}

extern "C" void kernel_launch(void* const* d_in, const int* in_sizes, int n_in,
                              void* d_out, int out_size) {
    const float* x = (const float*)d_in[0];
    const float* w = (const float*)d_in[1];
    float* z = (float*)d_out;
    cudaFuncSetAttribute(conv_mma<0>, cudaFuncAttributeMaxDynamicSharedMemorySize, CONV_SMEM);
    cudaFuncSetAttribute(conv_mma<1>, cudaFuncAttributeMaxDynamicSharedMemorySize, CONV_SMEM);
    cudaFuncSetAttribute(conv_mma<2>, cudaFuncAttributeMaxDynamicSharedMemorySize, CONV_SMEM);
    cudaFuncSetAttribute(conv_mma<3>, cudaFuncAttributeMaxDynamicSharedMemorySize, CONV_SMEM);
    roundx_kernel<<<16384, 256>>>(x);
    prep_kernel<<<CO_, 256>>>(w);
    conv_mma<3><<<dim3(NTILES, 2), 256, CONV_SMEM>>>();
    conv_mma<0><<<dim3(NTILES, 2), 256, CONV_SMEM>>>();
    conv_mma<1><<<dim3(NTILES, 2), 256, CONV_SMEM>>>();
    conv_mma<2><<<dim3(NTILES, 2), 256, CONV_SMEM>>>();
    blur_kernel<<<dim3(1, 1, B_ * CO_), dim3(32, 8)>>>(z);
}

// round 15
// speedup vs baseline: 1.1685x; 1.1685x over previous
#include <cuda_runtime.h>
#include <cstdint>

#define B_    8
#define CI_   512
#define CO_   256
#define HW_   64
#define NPIX  (HW_ * HW_)                     // 4096
#define YP_   136
#define YPP   (YP_ * YP_)
#define ZS_   128
#define NQUAD 65
#define NQ2   (NQUAD * NQUAD)                 // 4225
#define NTOT  (B_ * NQ2)                      // 33800 quads
#define MT_   128                             // M per CTA
#define NTILES ((NTOT + MT_ - 1) / MT_)       // 265
#define NCH   16
#define STG4  3072                            // float4 per stage: A 1024 + B 2048
#define CONV_SMEM (3 * STG4 * 16)             // 144 KB, 3-stage

// B frag layout: [tap][ch] blocks of 8192 floats: [kt][wn][p][lane][c]
__device__ float g_wf[9 * 16 * 8192];
__device__ float g_xcl[B_ * NPIX * CI_];           // channels-last tf32 x
__device__ float g_y[B_ * CO_ * YPP];              // padded intermediate (pad stays 0)

__device__ __forceinline__ uint32_t f2tf32(float f) {   // RN-to-even tf32 bits
    uint32_t u = __float_as_uint(f);
    u = u + 0xFFFu + ((u >> 13) & 1u);
    return u & 0xFFFFE000u;
}
__device__ __forceinline__ uint32_t sm_u32(const void* p) {
    uint32_t a;
    asm("{ .reg .u64 t; cvta.to.shared.u64 t, %1; cvt.u32.u64 %0, t; }" : "=r"(a) : "l"(p));
    return a;
}

// D(16x8) += A(16x8) * B(8x8), tf32. smem entry = {(m,k),(m,k+4),(m+8,k),(m+8,k+4)}
__device__ __forceinline__ void mma8(float* c, float4 a, float b0, float b1) {
    asm volatile(
        "mma.sync.aligned.m16n8k8.row.col.f32.tf32.tf32.f32 "
        "{%0,%1,%2,%3}, {%4,%5,%6,%7}, {%8,%9}, {%0,%1,%2,%3};"
        : "+f"(c[0]), "+f"(c[1]), "+f"(c[2]), "+f"(c[3])
        : "r"(__float_as_uint(a.x)), "r"(__float_as_uint(a.z)),
          "r"(__float_as_uint(a.y)), "r"(__float_as_uint(a.w)),
          "r"(__float_as_uint(b0)), "r"(__float_as_uint(b1)));
}

// ---------------- parity tables ----------------
__host__ __device__ constexpr int pc_nt(int P) { return P == 0 ? 4 : (P == 3 ? 1 : 2); }
__host__ __device__ constexpr int pc_sh(int P, int j) {
    return P == 0 ? j
         : P == 1 ? (j == 0 ? 1 : 3)
         : P == 2 ? (j == 0 ? 2 : 3)
         : 3;
}
__host__ __device__ constexpr int pc_tp(int P, int j) {
    return P == 0 ? (j == 0 ? 0 : j == 1 ? 2 : j == 2 ? 6 : 8)
         : P == 1 ? (j == 0 ? 1 : 7)
         : P == 2 ? (j == 0 ? 3 : 5)
         : 4;
}

// ---------------- x -> channels-last tf32 transpose ----------------
__global__ void xpose_kernel(const float* __restrict__ x) {
    __shared__ float t[32][33];
    const int bx = blockIdx.x, by = blockIdx.y, b = blockIdx.z;
    const int tx = threadIdx.x, ty = threadIdx.y;
#pragma unroll
    for (int j = 0; j < 4; j++)
        t[ty + j * 8][tx] = x[((size_t)(b * CI_ + by * 32 + ty + j * 8)) * NPIX + bx * 32 + tx];
    __syncthreads();
#pragma unroll
    for (int j = 0; j < 4; j++)
        g_xcl[((size_t)(b * NPIX + bx * 32 + ty + j * 8)) * CI_ + by * 32 + tx]
            = __uint_as_float(f2tf32(t[tx][ty + j * 8]));
}

// ---------------- prep: demodulate + flip + tf32-round, B frag layout with k-perm ----------------
// k-perm within each 8-ci kt-block: ci_local c <-> logical kl, c = 2*(kl&3) + (kl>>2)
__global__ void prep_kernel(const float* __restrict__ w) {
    __shared__ float red[256];
    const int o = blockIdx.x, tid = threadIdx.x;
    const float wsc = 1.0f / sqrtf((float)(CI_ * 9));
    const float* wo = w + o * (CI_ * 9);
    float s = 0.f;
    for (int idx = tid; idx < CI_ * 9; idx += 256) {
        float v = wo[idx] * wsc;
        s += v * v;
    }
    red[tid] = s;
    __syncthreads();
    for (int st = 128; st > 0; st >>= 1) {
        if (tid < st) red[tid] += red[tid + st];
        __syncthreads();
    }
    const float scale = wsc * rsqrtf(red[0] + 1e-6f);
    const int wn = o >> 6, c6 = o & 63, nt = c6 >> 3, cn = c6 & 7;
    const int p = nt >> 1;
    for (int idx = tid; idx < CI_ * 9; idx += 256) {
        int i = idx / 9, t = idx % 9, kh = t / 3, kw = t % 3;
        float v = wo[i * 9 + (2 - kh) * 3 + (2 - kw)] * scale;       // spatial flip
        int ch = i >> 5, k5 = i & 31, kt = k5 >> 3, c = k5 & 7;
        int kl = (c >> 1) | ((c & 1) << 2);                          // logical k (perm inverse)
        int lane = cn * 4 + (kl & 3), reg = kl >> 2;
        int cc = (nt & 1) * 2 + reg;
        g_wf[(size_t)(t * 16 + ch) * 8192
             + (size_t)(((kt * 4 + wn) * 4 + p) * 32 + lane) * 4 + cc]
            = __uint_as_float(f2tf32(v));
    }
}

// ---------------- transposed conv, one parity, TF32 mma.sync, 3-stage pipeline ----------------
template <int P>
__global__ void __launch_bounds__(256, 1) conv_mma() {
    constexpr int NT = pc_nt(P);
    constexpr int S  = NCH * NT;               // steps: (ch, tap) pairs
    extern __shared__ float4 smem4[];          // 3 stages x (A 1024 + B 2048) float4
    const uint32_t sm_base = sm_u32(smem4);

    const int tid = threadIdx.x, lane = tid & 31, warp = tid >> 5;
    const int wm = warp >> 2, wn = warp & 3;
    const int nt0 = blockIdx.x * MT_;

    // ---- staging precompute: per entry i: pixel bases (signed) + shift validity + k column ----
    int32_t pixb[4][2];
    uint32_t vmask = 0;                        // bit ((i*2+row)*4 + sh)
    int kOffE[4];
#pragma unroll
    for (int i = 0; i < 4; i++) {
        const int e = tid + i * 256;
        const int sl = e & 31;
        kOffE[i] = ((e >> 5) & 3) * 8 + (sl & 3) * 2;          // kt*8 + 2*klo (ci within ch)
        const int m0 = (e >> 7) * 16 + (sl >> 2);
#pragma unroll
        for (int row = 0; row < 2; row++) {
            const int gm = nt0 + m0 + row * 8;
            const int b = gm / NQ2, r = gm - b * NQ2;
            const int qa = r / NQUAD, qb = r - qa * NQUAD;
            const bool mok = gm < NTOT;
            pixb[i][row] = mok ? b * NPIX + (qa - 1) * HW_ + (qb - 1) : 0;
#pragma unroll
            for (int sh = 0; sh < 4; sh++) {
                const int iy = qa - 1 + (sh >> 1), ix = qb - 1 + (sh & 1);
                if (mok && (unsigned)iy < HW_ && (unsigned)ix < HW_)
                    vmask |= 1u << ((i * 2 + row) * 4 + sh);
            }
        }
    }

    // stage step st into pipeline stage stg
    auto stage = [&](int st, int stg) {
        const int ch = st / NT, j = st - ch * NT;
        const int sh = pc_sh(P, j);
        const int sdel = (sh >> 1) * HW_ + (sh & 1);
        const int cco = ch * 32;
        const uint32_t aB = sm_base + (uint32_t)(stg * STG4) * 16;
#pragma unroll
        for (int i = 0; i < 4; i++) {
            const uint32_t dst = aB + (uint32_t)((tid + i * 256) * 16);
#pragma unroll
            for (int row = 0; row < 2; row++) {
                const bool ok = (vmask >> ((i * 2 + row) * 4 + sh)) & 1u;
                const int off = ok ? ((pixb[i][row] + sdel) << 9) + cco + kOffE[i] : 0;
                const uint32_t okn = ok ? 8u : 0u;
                asm volatile("cp.async.ca.shared.global [%0], [%1], 8, %2;"
                             :: "r"(dst + row * 8), "l"(g_xcl + off), "r"(okn) : "memory");
            }
        }
        const int tap = pc_tp(P, j);
        const float4* bs = ((const float4*)g_wf) + (size_t)(tap * 16 + ch) * 2048 + tid;
        const uint32_t bB = aB + 1024 * 16;
        const uint32_t bd = bB + (uint32_t)(tid * 16);
#pragma unroll
        for (int t = 0; t < 8; t++)
            asm volatile("cp.async.ca.shared.global [%0], [%1], 16;"
                         :: "r"(bd + t * 4096), "l"(bs + t * 256) : "memory");
        asm volatile("cp.async.commit_group;" ::: "memory");
    };

    float acc[4][8][4];
#pragma unroll
    for (int q = 0; q < 4; q++)
#pragma unroll
        for (int n = 0; n < 8; n++)
#pragma unroll
            for (int r = 0; r < 4; r++) acc[q][n][r] = 0.f;

    stage(0, 0);
    stage(1, 1);

    int stg = 0;
    for (int st = 0; st < S; st++) {
        if (st + 2 < S) asm volatile("cp.async.wait_group 1;" ::: "memory");
        else            asm volatile("cp.async.wait_group 0;" ::: "memory");
        __syncthreads();
        const int aOff = stg * STG4;
        const int bOff = aOff + 1024;
#pragma unroll
        for (int kt = 0; kt < 4; kt++) {
            float4 af[4], bf[4];
#pragma unroll
            for (int q = 0; q < 4; q++)
                af[q] = smem4[aOff + ((wm * 4 + q) * 4 + kt) * 32 + lane];
#pragma unroll
            for (int p = 0; p < 4; p++)
                bf[p] = smem4[bOff + ((kt * 4 + wn) * 4 + p) * 32 + lane];
#pragma unroll
            for (int q = 0; q < 4; q++) {
                mma8(acc[q][0], af[q], bf[0].x, bf[0].y);
                mma8(acc[q][1], af[q], bf[0].z, bf[0].w);
                mma8(acc[q][2], af[q], bf[1].x, bf[1].y);
                mma8(acc[q][3], af[q], bf[1].z, bf[1].w);
                mma8(acc[q][4], af[q], bf[2].x, bf[2].y);
                mma8(acc[q][5], af[q], bf[2].z, bf[2].w);
                mma8(acc[q][6], af[q], bf[3].x, bf[3].y);
                mma8(acc[q][7], af[q], bf[3].z, bf[3].w);
            }
        }
        if (st + 2 < S) stage(st + 2, (st + 2) % 3);
        stg = (stg + 1 == 3) ? 0 : stg + 1;
    }

    // ---- epilogue: C frag -> g_y (parity pixel per quad) ----
#pragma unroll
    for (int q = 0; q < 4; q++) {
        size_t addr[2]; bool ok[2];
#pragma unroll
        for (int row = 0; row < 2; row++) {
            const int gm = nt0 + wm * 64 + q * 16 + (lane >> 2) + row * 8;
            const int b = gm / NQ2, r = gm - b * NQ2;
            const int qa = r / NQUAD, qb = r - qa * NQUAD;
            const int oy = 2 * qa + (P >> 1), ox = 2 * qb + (P & 1);
            ok[row] = (gm < NTOT) && (oy <= 128) && (ox <= 128);
            addr[row] = (size_t)(b * CO_) * YPP + (size_t)(oy + 1) * YP_ + (ox + 1);
        }
#pragma unroll
        for (int n = 0; n < 8; n++) {
            const int co = wn * 64 + n * 8 + 2 * (lane & 3);
            if (ok[0]) {
                size_t a0 = addr[0] + (size_t)co * YPP;
                g_y[a0] = acc[q][n][0];
                g_y[a0 + YPP] = acc[q][n][1];
            }
            if (ok[1]) {
                size_t a1 = addr[1] + (size_t)co * YPP;
                g_y[a1] = acc[q][n][2];
                g_y[a1 + YPP] = acc[q][n][3];
            }
        }
    }
}

// ---------------- depthwise 4x4 FIR blur, separable row-streaming ----------------
__global__ void blur_kernel(float* __restrict__ z) {
    const int cx = threadIdx.x;
    const int ry = threadIdx.y;
    const int bc = blockIdx.z;
    const int b = bc >> 8;
    const int col = bc & 255;
    const float* yb = g_y + (size_t)(b * CO_ + col) * YPP;
    float* zb = z + (size_t)(b * CO_ + col) * (ZS_ * ZS_);
    const int c0 = cx * 4;
    const int zy0 = ry * 16;

    float4 h0 = {}, h1 = {}, h2 = {};
#pragma unroll
    for (int k = 0; k < 19; k++) {
        const float* row = yb + (size_t)(zy0 + k) * YP_ + c0;
        float4 a = *(const float4*)row;
        float4 e = *(const float4*)(row + 4);
        float4 h;
        h.x = a.x + 3.f * a.y + 3.f * a.z + a.w;
        h.y = a.y + 3.f * a.z + 3.f * a.w + e.x;
        h.z = a.z + 3.f * a.w + 3.f * e.x + e.y;
        h.w = a.w + 3.f * e.x + 3.f * e.y + e.z;
        if (k >= 3) {
            float4 o;
            o.x = (h0.x + 3.f * h1.x + 3.f * h2.x + h.x) * 0.0625f;
            o.y = (h0.y + 3.f * h1.y + 3.f * h2.y + h.y) * 0.0625f;
            o.z = (h0.z + 3.f * h1.z + 3.f * h2.z + h.z) * 0.0625f;
            o.w = (h0.w + 3.f * h1.w + 3.f * h2.w + h.w) * 0.0625f;
            *(float4*)&zb[(size_t)(zy0 + k - 3) * ZS_ + c0] = o;
        }
        h0 = h1; h1 = h2; h2 = h;
    }
}

extern "C" void kernel_launch(void* const* d_in, const int* in_sizes, int n_in,
                              void* d_out, int out_size) {
    const float* x = (const float*)d_in[0];
    const float* w = (const float*)d_in[1];
    float* z = (float*)d_out;
    cudaFuncSetAttribute(conv_mma<0>, cudaFuncAttributeMaxDynamicSharedMemorySize, CONV_SMEM);
    cudaFuncSetAttribute(conv_mma<1>, cudaFuncAttributeMaxDynamicSharedMemorySize, CONV_SMEM);
    cudaFuncSetAttribute(conv_mma<2>, cudaFuncAttributeMaxDynamicSharedMemorySize, CONV_SMEM);
    cudaFuncSetAttribute(conv_mma<3>, cudaFuncAttributeMaxDynamicSharedMemorySize, CONV_SMEM);
    xpose_kernel<<<dim3(NPIX / 32, CI_ / 32, B_), dim3(32, 8)>>>(x);
    prep_kernel<<<CO_, 256>>>(w);
    conv_mma<3><<<NTILES, 256, CONV_SMEM>>>();
    conv_mma<0><<<NTILES, 256, CONV_SMEM>>>();
    conv_mma<1><<<NTILES, 256, CONV_SMEM>>>();
    conv_mma<2><<<NTILES, 256, CONV_SMEM>>>();
    blur_kernel<<<dim3(1, 1, B_ * CO_), dim3(32, 8)>>>(z);
}

// round 16
// speedup vs baseline: 1.3609x; 1.1646x over previous
#include <cuda_runtime.h>
#include <cstdint>

#define B_    8
#define CI_   512
#define CO_   256
#define HW_   64
#define NPIX  (HW_ * HW_)                     // 4096
#define YP_   136
#define YPP   (YP_ * YP_)
#define ZS_   128
#define NQUAD 65
#define NQ2   (NQUAD * NQUAD)                 // 4225
#define NTOT  (B_ * NQ2)                      // 33800 quads
#define MT_   128                             // M per CTA
#define NTILES ((NTOT + MT_ - 1) / MT_)       // 265
#define NCH   16
#define STG4  3072                            // float4 per stage: A 1024 + B 2048
#define CONV_SMEM (3 * STG4 * 16)             // 144 KB, 3-stage

// B frag layout: [tap][ch] blocks of 8192 floats: [kt][wn][p][lane][c]
__device__ float g_wf[9 * 16 * 8192];
__device__ float g_xcl[B_ * NPIX * CI_];           // channels-last tf32 x
__device__ float g_y[B_ * CO_ * YPP];              // padded intermediate (pad stays 0)

__device__ __forceinline__ uint32_t f2tf32(float f) {   // RN-to-even tf32 bits
    uint32_t u = __float_as_uint(f);
    u = u + 0xFFFu + ((u >> 13) & 1u);
    return u & 0xFFFFE000u;
}
__device__ __forceinline__ uint32_t sm_u32(const void* p) {
    uint32_t a;
    asm("{ .reg .u64 t; cvta.to.shared.u64 t, %1; cvt.u32.u64 %0, t; }" : "=r"(a) : "l"(p));
    return a;
}

// D(16x8) += A(16x8) * B(8x8), tf32. smem entry = {(m,k),(m,k+4),(m+8,k),(m+8,k+4)}
__device__ __forceinline__ void mma8(float* c, float4 a, float b0, float b1) {
    asm volatile(
        "mma.sync.aligned.m16n8k8.row.col.f32.tf32.tf32.f32 "
        "{%0,%1,%2,%3}, {%4,%5,%6,%7}, {%8,%9}, {%0,%1,%2,%3};"
        : "+f"(c[0]), "+f"(c[1]), "+f"(c[2]), "+f"(c[3])
        : "r"(__float_as_uint(a.x)), "r"(__float_as_uint(a.z)),
          "r"(__float_as_uint(a.y)), "r"(__float_as_uint(a.w)),
          "r"(__float_as_uint(b0)), "r"(__float_as_uint(b1)));
}

// ---------------- parity tables ----------------
__host__ __device__ constexpr int pc_nt(int P) { return P == 0 ? 4 : (P == 3 ? 1 : 2); }
__host__ __device__ constexpr int pc_sh(int P, int j) {
    return P == 0 ? j
         : P == 1 ? (j == 0 ? 1 : 3)
         : P == 2 ? (j == 0 ? 2 : 3)
         : 3;
}
__host__ __device__ constexpr int pc_tp(int P, int j) {
    return P == 0 ? (j == 0 ? 0 : j == 1 ? 2 : j == 2 ? 6 : 8)
         : P == 1 ? (j == 0 ? 1 : 7)
         : P == 2 ? (j == 0 ? 3 : 5)
         : 4;
}

// ---------------- x -> channels-last tf32 transpose ----------------
__global__ void xpose_kernel(const float* __restrict__ x) {
    __shared__ float t[32][33];
    const int bx = blockIdx.x, by = blockIdx.y, b = blockIdx.z;
    const int tx = threadIdx.x, ty = threadIdx.y;
#pragma unroll
    for (int j = 0; j < 4; j++)
        t[ty + j * 8][tx] = x[((size_t)(b * CI_ + by * 32 + ty + j * 8)) * NPIX + bx * 32 + tx];
    __syncthreads();
#pragma unroll
    for (int j = 0; j < 4; j++)
        g_xcl[((size_t)(b * NPIX + bx * 32 + ty + j * 8)) * CI_ + by * 32 + tx]
            = __uint_as_float(f2tf32(t[tx][ty + j * 8]));
}

// ---------------- prep: demodulate + flip + tf32-round, B frag layout with k-perm ----------------
__global__ void prep_kernel(const float* __restrict__ w) {
    __shared__ float red[256];
    const int o = blockIdx.x, tid = threadIdx.x;
    const float wsc = 1.0f / sqrtf((float)(CI_ * 9));
    const float* wo = w + o * (CI_ * 9);
    float s = 0.f;
    for (int idx = tid; idx < CI_ * 9; idx += 256) {
        float v = wo[idx] * wsc;
        s += v * v;
    }
    red[tid] = s;
    __syncthreads();
    for (int st = 128; st > 0; st >>= 1) {
        if (tid < st) red[tid] += red[tid + st];
        __syncthreads();
    }
    const float scale = wsc * rsqrtf(red[0] + 1e-6f);
    const int wn = o >> 6, c6 = o & 63, nt = c6 >> 3, cn = c6 & 7;
    const int p = nt >> 1;
    for (int idx = tid; idx < CI_ * 9; idx += 256) {
        int i = idx / 9, t = idx % 9, kh = t / 3, kw = t % 3;
        float v = wo[i * 9 + (2 - kh) * 3 + (2 - kw)] * scale;       // spatial flip
        int ch = i >> 5, k5 = i & 31, kt = k5 >> 3, c = k5 & 7;
        int kl = (c >> 1) | ((c & 1) << 2);                          // logical k (perm inverse)
        int lane = cn * 4 + (kl & 3), reg = kl >> 2;
        int cc = (nt & 1) * 2 + reg;
        g_wf[(size_t)(t * 16 + ch) * 8192
             + (size_t)(((kt * 4 + wn) * 4 + p) * 32 + lane) * 4 + cc]
            = __uint_as_float(f2tf32(v));
    }
}

// ---------------- conv body: one parity, TF32 mma.sync, 3-stage + kt frag pipeline ----------------
template <int P>
__device__ __forceinline__ void conv_body(float4* smem4) {
    constexpr int NT = pc_nt(P);
    constexpr int S  = NCH * NT;               // steps: (ch, tap) pairs
    const uint32_t sm_base = sm_u32(smem4);

    const int tid = threadIdx.x, lane = tid & 31, warp = tid >> 5;
    const int wm = warp >> 2, wn = warp & 3;
    const int nt0 = blockIdx.x * MT_;

    // ---- staging precompute ----
    int32_t pixb[4][2];
    uint32_t vmask = 0;                        // bit ((i*2+row)*4 + sh)
    int kOffE[4];
#pragma unroll
    for (int i = 0; i < 4; i++) {
        const int e = tid + i * 256;
        const int sl = e & 31;
        kOffE[i] = ((e >> 5) & 3) * 8 + (sl & 3) * 2;          // kt*8 + 2*klo
        const int m0 = (e >> 7) * 16 + (sl >> 2);
#pragma unroll
        for (int row = 0; row < 2; row++) {
            const int gm = nt0 + m0 + row * 8;
            const int b = gm / NQ2, r = gm - b * NQ2;
            const int qa = r / NQUAD, qb = r - qa * NQUAD;
            const bool mok = gm < NTOT;
            pixb[i][row] = mok ? b * NPIX + (qa - 1) * HW_ + (qb - 1) : 0;
#pragma unroll
            for (int sh = 0; sh < 4; sh++) {
                const int iy = qa - 1 + (sh >> 1), ix = qb - 1 + (sh & 1);
                if (mok && (unsigned)iy < HW_ && (unsigned)ix < HW_)
                    vmask |= 1u << ((i * 2 + row) * 4 + sh);
            }
        }
    }

    auto stage = [&](int st, int stg) {
        const int ch = st / NT, j = st - ch * NT;
        const int sh = pc_sh(P, j);
        const int sdel = (sh >> 1) * HW_ + (sh & 1);
        const int cco = ch * 32;
        const uint32_t aB = sm_base + (uint32_t)(stg * STG4) * 16;
#pragma unroll
        for (int i = 0; i < 4; i++) {
            const uint32_t dst = aB + (uint32_t)((tid + i * 256) * 16);
#pragma unroll
            for (int row = 0; row < 2; row++) {
                const bool ok = (vmask >> ((i * 2 + row) * 4 + sh)) & 1u;
                const int off = ok ? ((pixb[i][row] + sdel) << 9) + cco + kOffE[i] : 0;
                const uint32_t okn = ok ? 8u : 0u;
                asm volatile("cp.async.ca.shared.global [%0], [%1], 8, %2;"
                             :: "r"(dst + row * 8), "l"(g_xcl + off), "r"(okn) : "memory");
            }
        }
        const int tap = pc_tp(P, j);
        const float4* bs = ((const float4*)g_wf) + (size_t)(tap * 16 + ch) * 2048 + tid;
        const uint32_t bd = aB + 1024 * 16 + (uint32_t)(tid * 16);
#pragma unroll
        for (int t = 0; t < 8; t++)
            asm volatile("cp.async.ca.shared.global [%0], [%1], 16;"
                         :: "r"(bd + t * 4096), "l"(bs + t * 256) : "memory");
        asm volatile("cp.async.commit_group;" ::: "memory");
    };

    float acc[4][8][4];
#pragma unroll
    for (int q = 0; q < 4; q++)
#pragma unroll
        for (int n = 0; n < 8; n++)
#pragma unroll
            for (int r = 0; r < 4; r++) acc[q][n][r] = 0.f;

    stage(0, 0);
    stage(1, 1);

    int stg = 0;
    for (int st = 0; st < S; st++) {
        if (st + 2 < S) asm volatile("cp.async.wait_group 1;" ::: "memory");
        else            asm volatile("cp.async.wait_group 0;" ::: "memory");
        __syncthreads();
        if (st + 2 < S) stage(st + 2, (st + 2) % 3);   // slot free: last used by step st-1
        const int aOff = stg * STG4;
        const int bOff = aOff + 1024;
        // kt register double-buffer: preload kt+1 frags during kt's MMAs
        float4 af[2][4], bf[2][4];
#pragma unroll
        for (int q = 0; q < 4; q++) af[0][q] = smem4[aOff + ((wm * 4 + q) * 4 + 0) * 32 + lane];
#pragma unroll
        for (int p = 0; p < 4; p++) bf[0][p] = smem4[bOff + ((0 * 4 + wn) * 4 + p) * 32 + lane];
#pragma unroll
        for (int kt = 0; kt < 4; kt++) {
            const int cur = kt & 1, nxt = cur ^ 1;
            if (kt < 3) {
#pragma unroll
                for (int q = 0; q < 4; q++)
                    af[nxt][q] = smem4[aOff + ((wm * 4 + q) * 4 + kt + 1) * 32 + lane];
#pragma unroll
                for (int p = 0; p < 4; p++)
                    bf[nxt][p] = smem4[bOff + (((kt + 1) * 4 + wn) * 4 + p) * 32 + lane];
            }
#pragma unroll
            for (int q = 0; q < 4; q++) {
                mma8(acc[q][0], af[cur][q], bf[cur][0].x, bf[cur][0].y);
                mma8(acc[q][1], af[cur][q], bf[cur][0].z, bf[cur][0].w);
                mma8(acc[q][2], af[cur][q], bf[cur][1].x, bf[cur][1].y);
                mma8(acc[q][3], af[cur][q], bf[cur][1].z, bf[cur][1].w);
                mma8(acc[q][4], af[cur][q], bf[cur][2].x, bf[cur][2].y);
                mma8(acc[q][5], af[cur][q], bf[cur][2].z, bf[cur][2].w);
                mma8(acc[q][6], af[cur][q], bf[cur][3].x, bf[cur][3].y);
                mma8(acc[q][7], af[cur][q], bf[cur][3].z, bf[cur][3].w);
            }
        }
        stg = (stg + 1 == 3) ? 0 : stg + 1;
    }

    // ---- epilogue: C frag -> g_y (parity pixel per quad) ----
#pragma unroll
    for (int q = 0; q < 4; q++) {
        size_t addr[2]; bool ok[2];
#pragma unroll
        for (int row = 0; row < 2; row++) {
            const int gm = nt0 + wm * 64 + q * 16 + (lane >> 2) + row * 8;
            const int b = gm / NQ2, r = gm - b * NQ2;
            const int qa = r / NQUAD, qb = r - qa * NQUAD;
            const int oy = 2 * qa + (P >> 1), ox = 2 * qb + (P & 1);
            ok[row] = (gm < NTOT) && (oy <= 128) && (ox <= 128);
            addr[row] = (size_t)(b * CO_) * YPP + (size_t)(oy + 1) * YP_ + (ox + 1);
        }
#pragma unroll
        for (int n = 0; n < 8; n++) {
            const int co = wn * 64 + n * 8 + 2 * (lane & 3);
            if (ok[0]) {
                size_t a0 = addr[0] + (size_t)co * YPP;
                g_y[a0] = acc[q][n][0];
                g_y[a0 + YPP] = acc[q][n][1];
            }
            if (ok[1]) {
                size_t a1 = addr[1] + (size_t)co * YPP;
                g_y[a1] = acc[q][n][2];
                g_y[a1 + YPP] = acc[q][n][3];
            }
        }
    }
}

// single fused launch: blockIdx.y selects parity
__global__ void __launch_bounds__(256, 1) conv_all() {
    extern __shared__ float4 smem4[];
    switch (blockIdx.y) {
        case 0: conv_body<0>(smem4); break;
        case 1: conv_body<1>(smem4); break;
        case 2: conv_body<2>(smem4); break;
        default: conv_body<3>(smem4); break;
    }
}

// ---------------- depthwise 4x4 FIR blur, separable row-streaming ----------------
__global__ void blur_kernel(float* __restrict__ z) {
    const int cx = threadIdx.x;
    const int ry = threadIdx.y;
    const int bc = blockIdx.z;
    const int b = bc >> 8;
    const int col = bc & 255;
    const float* yb = g_y + (size_t)(b * CO_ + col) * YPP;
    float* zb = z + (size_t)(b * CO_ + col) * (ZS_ * ZS_);
    const int c0 = cx * 4;
    const int zy0 = ry * 16;

    float4 h0 = {}, h1 = {}, h2 = {};
#pragma unroll
    for (int k = 0; k < 19; k++) {
        const float* row = yb + (size_t)(zy0 + k) * YP_ + c0;
        float4 a = *(const float4*)row;
        float4 e = *(const float4*)(row + 4);
        float4 h;
        h.x = a.x + 3.f * a.y + 3.f * a.z + a.w;
        h.y = a.y + 3.f * a.z + 3.f * a.w + e.x;
        h.z = a.z + 3.f * a.w + 3.f * e.x + e.y;
        h.w = a.w + 3.f * e.x + 3.f * e.y + e.z;
        if (k >= 3) {
            float4 o;
            o.x = (h0.x + 3.f * h1.x + 3.f * h2.x + h.x) * 0.0625f;
            o.y = (h0.y + 3.f * h1.y + 3.f * h2.y + h.y) * 0.0625f;
            o.z = (h0.z + 3.f * h1.z + 3.f * h2.z + h.z) * 0.0625f;
            o.w = (h0.w + 3.f * h1.w + 3.f * h2.w + h.w) * 0.0625f;
            *(float4*)&zb[(size_t)(zy0 + k - 3) * ZS_ + c0] = o;
        }
        h0 = h1; h1 = h2; h2 = h;
    }
}

extern "C" void kernel_launch(void* const* d_in, const int* in_sizes, int n_in,
                              void* d_out, int out_size) {
    const float* x = (const float*)d_in[0];
    const float* w = (const float*)d_in[1];
    float* z = (float*)d_out;
    cudaFuncSetAttribute(conv_all, cudaFuncAttributeMaxDynamicSharedMemorySize, CONV_SMEM);
    xpose_kernel<<<dim3(NPIX / 32, CI_ / 32, B_), dim3(32, 8)>>>(x);
    prep_kernel<<<CO_, 256>>>(w);
    conv_all<<<dim3(NTILES, 4), 256, CONV_SMEM>>>();
    blur_kernel<<<dim3(1, 1, B_ * CO_), dim3(32, 8)>>>(z);
}